// round 14
// baseline (speedup 1.0000x reference)
#include <cuda_runtime.h>
#include <cuda_fp16.h>

#define NHID 32

// fp32 folded coefficients (tail path): per j: 9 K coeffs + W2[j][0..1] + pad
__device__ float g_const[NHID * 12];
// Main-GEMM B fragments for mma.sync.m16n8k8: [ntile][lane], 1 reg each:
// lane (g,t) holds half2( K[1+2t][j], K[2+2t][j] ), j = nt*8+g  (features 1..8)
__device__ unsigned int g_Bfrag[4][32];
// Accumulator init (constant feature): [ntile][lane][2] fp32:
// component c = K00b[nt*8 + 2*(lane&3) + c]  (same for all g)
__device__ float g_InitF[4][32][2];
// Epilogue B2 fragments: [kstep][reg][lane]. B2 is 16x8 (k=hidden, n=8):
// n 0,1 = f16(W2[:,n]); n 2,3 = f16((W2[:,n-2]-f16(W2[:,n-2]))*4096); n>=4 = 0.
__device__ unsigned int g_B2frag[2][2][32];

struct cpx { float x, y; };

__device__ __forceinline__ void apply1q(cpx* s, cpx m00, cpx m01, cpx m10, cpx m11, int wire)
{
    int st = 1 << (2 - wire);
    for (int i = 0; i < 8; i++) {
        if (i & st) continue;
        cpx a = s[i], b = s[i + st];
        cpx n0 = { m00.x*a.x - m00.y*a.y + m01.x*b.x - m01.y*b.y,
                   m00.x*a.y + m00.y*a.x + m01.x*b.y + m01.y*b.x };
        cpx n1 = { m10.x*a.x - m10.y*a.y + m11.x*b.x - m11.y*b.y,
                   m10.x*a.y + m10.y*a.x + m11.x*b.y + m11.y*b.x };
        s[i] = n0; s[i + st] = n1;
    }
}

__device__ __forceinline__ void applyCRX(cpx* s, float c, float sn, int ctrl, int tgt)
{
    int cs = 1 << (2 - ctrl), ts = 1 << (2 - tgt);
    for (int i = 0; i < 8; i++) {
        if (!(i & cs) || (i & ts)) continue;
        cpx a = s[i], b = s[i + ts];
        s[i]      = { c*a.x + sn*b.y, c*a.y - sn*b.x };
        s[i + ts] = { c*b.x + sn*a.y, c*b.y - sn*a.x };
    }
}

__global__ void setup_kernel(const float* __restrict__ theta,
                             const float* __restrict__ W1,
                             const float* __restrict__ b1,
                             const float* __restrict__ W2)
{
    __shared__ cpx Vs[4][8];
    int tid = threadIdx.x;

    if (tid < 4) {
        cpx s[8];
        for (int i = 0; i < 8; i++) s[i] = {0.f, 0.f};
        s[tid * 2] = {1.f, 0.f};
        float c, sn;
        sincosf(0.5f * theta[0], &sn, &c);
        apply1q(s, {c,0.f},{0.f,-sn},{0.f,-sn},{c,0.f}, 0);
        sincosf(0.5f * theta[1], &sn, &c);
        apply1q(s, {c,0.f},{-sn,0.f},{sn,0.f},{c,0.f}, 1);
        sincosf(0.5f * theta[2], &sn, &c);
        apply1q(s, {c,-sn},{0.f,0.f},{0.f,0.f},{c,sn}, 2);
        sincosf(0.5f * theta[3], &sn, &c);
        applyCRX(s, c, sn, 0, 1);
        sincosf(0.5f * theta[4], &sn, &c);
        apply1q(s, {c,0.f},{-sn,0.f},{sn,0.f},{c,0.f}, 2);
        sincosf(0.5f * theta[5], &sn, &c);
        apply1q(s, {c,0.f},{0.f,-sn},{0.f,-sn},{c,0.f}, 1);
        sincosf(0.5f * theta[6], &sn, &c);
        applyCRX(s, c, sn, 1, 2);
        sincosf(0.5f * theta[7], &sn, &c);
        apply1q(s, {c,-sn},{0.f,0.f},{0.f,0.f},{c,sn}, 0);
        for (int k = 0; k < 8; k++)
            Vs[tid][k] = (tid >= 2) ? cpx{ s[k].y, -s[k].x } : s[k]; // * (-i)
    }
    __syncwarp();

    int j = tid;
    float M[4][4];
    for (int a = 0; a < 4; a++)
        for (int b = 0; b < 4; b++) {
            float m = 0.f;
            for (int k = 0; k < 8; k++)
                m += W1[k * NHID + j] * (Vs[a][k].x * Vs[b][k].x + Vs[a][k].y * Vs[b][k].y);
            M[a][b] = m;
        }

    const float R[2][2][3] = { { {0.5f, 0.5f, 0.f}, {0.f, 0.f, 0.5f} },
                               { {0.f, 0.f, 0.5f}, {0.5f, -0.5f, 0.f} } };
    float K[3][3] = { {0.f,0.f,0.f},{0.f,0.f,0.f},{0.f,0.f,0.f} };
    for (int a = 0; a < 4; a++)
        for (int b = 0; b < 4; b++) {
            int ia = a >> 1, ja = a & 1, ib = b >> 1, jb = b & 1;
            float Mab = M[a][b];
            for (int m = 0; m < 3; m++)
                for (int n = 0; n < 3; n++)
                    K[m][n] += Mab * R[ia][ib][m] * R[ja][jb][n];
        }
    K[0][0] += b1[j];

    float cf[9];
    for (int t = 0; t < 9; t++) cf[t] = K[t / 3][t % 3];

    for (int t = 0; t < 9; t++) g_const[j * 12 + t] = cf[t];
    g_const[j * 12 + 9]  = W2[j * 2 + 0];
    g_const[j * 12 + 10] = W2[j * 2 + 1];
    g_const[j * 12 + 11] = 0.f;

    // main-GEMM k8 B fragments: rows = features 1..8 (f16), col j
    {
        int nt = j >> 3, g = j & 7;
        for (int t = 0; t < 4; t++) {
            __half2 h2 = __floats2half2_rn(cf[1 + 2 * t], cf[2 + 2 * t]);
            g_Bfrag[nt][g * 4 + t] = *reinterpret_cast<unsigned int*>(&h2);
        }
    }

    // accumulator init: K00b[j] (exact fp32) goes to lanes with 2t(+1) == j&7
    {
        int nt = j >> 3, c = j & 7;
        for (int g = 0; g < 8; g++)
            g_InitF[nt][g * 4 + (c >> 1)][c & 1] = cf[0];
    }

    // epilogue B2 fragments (exact W2 via scaled-lo n-columns)
    {
        int g = tid >> 2, t = tid & 3;
        for (int ks = 0; ks < 2; ks++)
            for (int r = 0; r < 2; r++) {
                int k0 = ks * 16 + 2 * t + r * 8;
                float v0 = 0.f, v1 = 0.f;
                if (g < 2) {
                    v0 = W2[k0 * 2 + g];
                    v1 = W2[(k0 + 1) * 2 + g];
                } else if (g < 4) {
                    int c = g - 2;
                    float w0f = W2[k0 * 2 + c];
                    float w1f = W2[(k0 + 1) * 2 + c];
                    v0 = (w0f - __half2float(__float2half_rn(w0f))) * 4096.f;
                    v1 = (w1f - __half2float(__float2half_rn(w1f))) * 4096.f;
                }
                __half2 h2 = __floats2half2_rn(v0, v1);
                g_B2frag[ks][r][tid] = *reinterpret_cast<unsigned int*>(&h2);
            }
    }
}

__device__ __forceinline__ void mma16816(float c[4],
                                         unsigned a0, unsigned a1, unsigned a2, unsigned a3,
                                         unsigned b0, unsigned b1)
{
    asm volatile(
        "mma.sync.aligned.m16n8k16.row.col.f32.f16.f16.f32 "
        "{%0,%1,%2,%3}, {%4,%5,%6,%7}, {%8,%9}, {%0,%1,%2,%3};"
        : "+f"(c[0]), "+f"(c[1]), "+f"(c[2]), "+f"(c[3])
        : "r"(a0), "r"(a1), "r"(a2), "r"(a3), "r"(b0), "r"(b1));
}

__device__ __forceinline__ void mma16808(float c[4],
                                         unsigned a0, unsigned a1, unsigned b0)
{
    asm volatile(
        "mma.sync.aligned.m16n8k8.row.col.f32.f16.f16.f32 "
        "{%0,%1,%2,%3}, {%4,%5}, {%6}, {%0,%1,%2,%3};"
        : "+f"(c[0]), "+f"(c[1]), "+f"(c[2]), "+f"(c[3])
        : "r"(a0), "r"(a1), "r"(b0));
}

__device__ __forceinline__ void ldmatrix_x4(unsigned& a0, unsigned& a1,
                                            unsigned& a2, unsigned& a3,
                                            unsigned saddr)
{
    asm volatile(
        "ldmatrix.sync.aligned.m8n8.x4.shared.b16 {%0,%1,%2,%3}, [%4];"
        : "=r"(a0), "=r"(a1), "=r"(a2), "=r"(a3) : "r"(saddr));
}

// One warp = 128 samples = 4 iterations of 32, all staged before one
// syncwarp (8 independent tile chains). Hidden layer: m16n8k8 f16 MMA with
// the constant term in fp32 accumulator init (exact bias). Output layer:
// MMA on f16(relu(H)) with exact W2 via scaled-lo n-columns.
#define ITER 4
__global__ void __launch_bounds__(256, 4)
qmlp_mma(const float* __restrict__ x,
         const float* __restrict__ b2,
         float* __restrict__ out, int B)
{
    // 8 halves (16 B) per row: uint4-aligned, STS/LDSM conflict-free
    __shared__ __align__(16) __half sA[8][ITER][32 * 8];

    int lane = threadIdx.x & 31;
    int warp = threadIdx.x >> 5;
    long long G = (long long)blockIdx.x * 8 + warp;
    long long wbase = G * (32 * ITER);
    if (wbase >= B) return;

    int g = lane >> 2, t = lane & 3;
    float bias0 = __ldg(&b2[0]);
    float bias1 = __ldg(&b2[1]);

    // hoisted uniform operands
    unsigned bf[4];
    #pragma unroll
    for (int nt = 0; nt < 4; nt++)
        bf[nt] = __ldg(&g_Bfrag[nt][lane]);
    float2 iv[4];
    #pragma unroll
    for (int nt = 0; nt < 4; nt++)
        iv[nt] = __ldg(reinterpret_cast<const float2*>(&g_InitF[nt][lane][0]));
    unsigned b2f[2][2];
    #pragma unroll
    for (int ks = 0; ks < 2; ks++) {
        b2f[ks][0] = __ldg(&g_B2frag[ks][0][lane]);
        b2f[ks][1] = __ldg(&g_B2frag[ks][1][lane]);
    }

    const __half2 hz = __floats2half2_rn(0.f, 0.f);
    const float SCL = 1.f / 4096.f;

    if (wbase + 32 * ITER <= B) {
        // ---- stage all ITER halves, then one syncwarp ----
        #pragma unroll
        for (int it = 0; it < ITER; it++) {
            long long S = wbase + (long long)it * 32 + lane;
            float xa = __ldg(&x[S * 3]);
            float xb = __ldg(&x[S * 3 + 1]);      // x[...+2] is a global phase
            float s0n, c0n, s1n, c1n;
            __sincosf(xa, &s0n, &c0n);
            __sincosf(xb, &s1n, &c1n);
            // features 1..8 (constant term lives in the accumulator)
            __half2 h2;
            unsigned w0, w1, w2, w3;
            #define PACK(a, b) (h2 = __floats2half2_rn((a), (b)), *reinterpret_cast<unsigned*>(&h2))
            w0 = PACK(c1n, s1n);
            w1 = PACK(c0n, c0n * c1n);
            w2 = PACK(c0n * s1n, s0n);
            w3 = PACK(s0n * c1n, s0n * s1n);
            #undef PACK
            *reinterpret_cast<uint4*>(&sA[warp][it][lane * 8]) =
                make_uint4(w0, w1, w2, w3);
        }
        __syncwarp();

        // ---- 8 independent tile chains (ITER x 2 tiles) ----
        #pragma unroll
        for (int it = 0; it < ITER; it++) {
            unsigned sbase = (unsigned)__cvta_generic_to_shared(&sA[warp][it][0]);
            // one ldmatrix.x4 loads BOTH tiles' A fragments (32 rows x 8 cols)
            unsigned r0, r1, r2, r3;
            ldmatrix_x4(r0, r1, r2, r3, sbase + (unsigned)lane * 16u);

            #pragma unroll
            for (int tile = 0; tile < 2; tile++) {
                unsigned a0 = tile ? r2 : r0;
                unsigned a1 = tile ? r3 : r1;

                float acc[4][4];
                #pragma unroll
                for (int nt = 0; nt < 4; nt++) {
                    acc[nt][0] = iv[nt].x;
                    acc[nt][1] = iv[nt].y;
                    acc[nt][2] = iv[nt].x;
                    acc[nt][3] = iv[nt].y;
                }
                #pragma unroll
                for (int nt = 0; nt < 4; nt++)
                    mma16808(acc[nt], a0, a1, bf[nt]);

                // epilogue on the tensor pipe
                unsigned hp[4][2];
                #pragma unroll
                for (int nt = 0; nt < 4; nt++) {
                    __half2 t01 = __floats2half2_rn(acc[nt][0], acc[nt][1]);
                    __half2 t23 = __floats2half2_rn(acc[nt][2], acc[nt][3]);
                    t01 = __hmax2(t01, hz);
                    t23 = __hmax2(t23, hz);
                    hp[nt][0] = *reinterpret_cast<unsigned*>(&t01);
                    hp[nt][1] = *reinterpret_cast<unsigned*>(&t23);
                }
                float o[4] = { 0.f, 0.f, 0.f, 0.f };
                mma16816(o, hp[0][0], hp[0][1], hp[1][0], hp[1][1], b2f[0][0], b2f[0][1]);
                mma16816(o, hp[2][0], hp[2][1], hp[3][0], hp[3][1], b2f[1][0], b2f[1][1]);

                // t=0: W2_hi (n=0,1); t=1: scaled W2_lo (n=2,3)
                float cr0 = __shfl_xor_sync(0xffffffffu, o[0], 1);
                float cr1 = __shfl_xor_sync(0xffffffffu, o[1], 1);
                float cr2 = __shfl_xor_sync(0xffffffffu, o[2], 1);
                float cr3 = __shfl_xor_sync(0xffffffffu, o[3], 1);

                if (t == 0) {
                    long long rr = wbase + (long long)it * 32 + tile * 16 + g;
                    float2* ov = reinterpret_cast<float2*>(out);
                    ov[rr]     = make_float2(fmaf(cr0, SCL, o[0]) + bias0,
                                             fmaf(cr1, SCL, o[1]) + bias1);
                    ov[rr + 8] = make_float2(fmaf(cr2, SCL, o[2]) + bias0,
                                             fmaf(cr3, SCL, o[3]) + bias1);
                }
            }
        }
    } else {
        // scalar fp32 tail
        for (long long s = wbase + lane; s < B; s += 32) {
            float xx0 = x[s * 3], xx1 = x[s * 3 + 1];
            float cc0, ss0, cc1, ss1;
            __sincosf(xx0, &ss0, &cc0);
            __sincosf(xx1, &ss1, &cc1);
            float o0 = bias0, o1 = bias1;
            for (int j = 0; j < NHID; j++) {
                const float* K = &g_const[j * 12];
                float t0 = K[0] + K[1]*cc1 + K[2]*ss1;
                float t1 = K[3] + K[4]*cc1 + K[5]*ss1;
                float t2 = K[6] + K[7]*cc1 + K[8]*ss1;
                float h = fmaxf(t0 + cc0*t1 + ss0*t2, 0.f);
                o0 += h * K[9];
                o1 += h * K[10];
            }
            out[s * 2]     = o0;
            out[s * 2 + 1] = o1;
        }
    }
}

extern "C" void kernel_launch(void* const* d_in, const int* in_sizes, int n_in,
                              void* d_out, int out_size)
{
    const float* x     = (const float*)d_in[0];
    const float* theta = (const float*)d_in[1];
    const float* W1    = (const float*)d_in[2];
    const float* b1    = (const float*)d_in[3];
    const float* W2    = (const float*)d_in[4];
    const float* b2    = (const float*)d_in[5];
    int B = in_sizes[0] / 3;

    setup_kernel<<<1, 32>>>(theta, W1, b1, W2);

    long long wgroups = ((long long)B + 32 * ITER - 1) / (32 * ITER);
    int nblocks = (int)((wgroups + 7) / 8);
    qmlp_mma<<<nblocks, 256>>>(x, b2, (float*)d_out, B);
}

// round 15
// speedup vs baseline: 1.2092x; 1.2092x over previous
#include <cuda_runtime.h>
#include <cuda_fp16.h>

#define NHID 32

// fp32 folded coefficients (tail path): per j: 9 K coeffs + W2[j][0..1] + pad
__device__ float g_const[NHID * 12];
// Main-GEMM B fragments for mma.sync.m16n8k16 (single k-step):
// [ntile][reg][lane]; KK rows 0-8 = f16(K), rows 9-15 = 0.
__device__ unsigned int g_Bfrag[4][2][32];
// Epilogue B2 fragments: [kstep][reg][lane]. B2 is 16x8 (k=hidden, n=8):
// n 0,1 = f16(W2[:,n]); n 2,3 = f16((W2[:,n-2]-f16(W2[:,n-2]))*4096); n>=4 = 0.
__device__ unsigned int g_B2frag[2][2][32];

struct cpx { float x, y; };

__device__ __forceinline__ void apply1q(cpx* s, cpx m00, cpx m01, cpx m10, cpx m11, int wire)
{
    int st = 1 << (2 - wire);
    for (int i = 0; i < 8; i++) {
        if (i & st) continue;
        cpx a = s[i], b = s[i + st];
        cpx n0 = { m00.x*a.x - m00.y*a.y + m01.x*b.x - m01.y*b.y,
                   m00.x*a.y + m00.y*a.x + m01.x*b.y + m01.y*b.x };
        cpx n1 = { m10.x*a.x - m10.y*a.y + m11.x*b.x - m11.y*b.y,
                   m10.x*a.y + m10.y*a.x + m11.x*b.y + m11.y*b.x };
        s[i] = n0; s[i + st] = n1;
    }
}

__device__ __forceinline__ void applyCRX(cpx* s, float c, float sn, int ctrl, int tgt)
{
    int cs = 1 << (2 - ctrl), ts = 1 << (2 - tgt);
    for (int i = 0; i < 8; i++) {
        if (!(i & cs) || (i & ts)) continue;
        cpx a = s[i], b = s[i + ts];
        s[i]      = { c*a.x + sn*b.y, c*a.y - sn*b.x };
        s[i + ts] = { c*b.x + sn*a.y, c*b.y - sn*a.x };
    }
}

__global__ void setup_kernel(const float* __restrict__ theta,
                             const float* __restrict__ W1,
                             const float* __restrict__ b1,
                             const float* __restrict__ W2)
{
    __shared__ cpx Vs[4][8];
    int tid = threadIdx.x;

    if (tid < 4) {
        cpx s[8];
        for (int i = 0; i < 8; i++) s[i] = {0.f, 0.f};
        s[tid * 2] = {1.f, 0.f};
        float c, sn;
        __sincosf(0.5f * theta[0], &sn, &c);
        apply1q(s, {c,0.f},{0.f,-sn},{0.f,-sn},{c,0.f}, 0);
        __sincosf(0.5f * theta[1], &sn, &c);
        apply1q(s, {c,0.f},{-sn,0.f},{sn,0.f},{c,0.f}, 1);
        __sincosf(0.5f * theta[2], &sn, &c);
        apply1q(s, {c,-sn},{0.f,0.f},{0.f,0.f},{c,sn}, 2);
        __sincosf(0.5f * theta[3], &sn, &c);
        applyCRX(s, c, sn, 0, 1);
        __sincosf(0.5f * theta[4], &sn, &c);
        apply1q(s, {c,0.f},{-sn,0.f},{sn,0.f},{c,0.f}, 2);
        __sincosf(0.5f * theta[5], &sn, &c);
        apply1q(s, {c,0.f},{0.f,-sn},{0.f,-sn},{c,0.f}, 1);
        __sincosf(0.5f * theta[6], &sn, &c);
        applyCRX(s, c, sn, 1, 2);
        __sincosf(0.5f * theta[7], &sn, &c);
        apply1q(s, {c,-sn},{0.f,0.f},{0.f,0.f},{c,sn}, 0);
        for (int k = 0; k < 8; k++)
            Vs[tid][k] = (tid >= 2) ? cpx{ s[k].y, -s[k].x } : s[k]; // * (-i)
    }
    __syncwarp();

    int j = tid;
    float M[4][4];
    for (int a = 0; a < 4; a++)
        for (int b = 0; b < 4; b++) {
            float m = 0.f;
            for (int k = 0; k < 8; k++)
                m += W1[k * NHID + j] * (Vs[a][k].x * Vs[b][k].x + Vs[a][k].y * Vs[b][k].y);
            M[a][b] = m;
        }

    const float R[2][2][3] = { { {0.5f, 0.5f, 0.f}, {0.f, 0.f, 0.5f} },
                               { {0.f, 0.f, 0.5f}, {0.5f, -0.5f, 0.f} } };
    float K[3][3] = { {0.f,0.f,0.f},{0.f,0.f,0.f},{0.f,0.f,0.f} };
    for (int a = 0; a < 4; a++)
        for (int b = 0; b < 4; b++) {
            int ia = a >> 1, ja = a & 1, ib = b >> 1, jb = b & 1;
            float Mab = M[a][b];
            for (int m = 0; m < 3; m++)
                for (int n = 0; n < 3; n++)
                    K[m][n] += Mab * R[ia][ib][m] * R[ja][jb][n];
        }
    K[0][0] += b1[j];

    float cf[9];
    for (int t = 0; t < 9; t++) cf[t] = K[t / 3][t % 3];

    for (int t = 0; t < 9; t++) g_const[j * 12 + t] = cf[t];
    g_const[j * 12 + 9]  = W2[j * 2 + 0];
    g_const[j * 12 + 10] = W2[j * 2 + 1];
    g_const[j * 12 + 11] = 0.f;

    // main-GEMM fragments: single k-step, B = f16(K), rows 9-15 zero
    {
        int nt = j >> 3, g = j & 7;
        for (int r = 0; r < 2; r++)
            for (int t = 0; t < 4; t++) {
                int r0 = 2 * t + r * 8;
                float v0 = (r0     < 9) ? cf[r0]     : 0.f;
                float v1 = (r0 + 1 < 9) ? cf[r0 + 1] : 0.f;
                __half2 h2 = __floats2half2_rn(v0, v1);
                g_Bfrag[nt][r][g * 4 + t] = *reinterpret_cast<unsigned int*>(&h2);
            }
    }

    // epilogue B2 fragments (exact W2 via scaled-lo n-columns)
    {
        int g = tid >> 2, t = tid & 3;
        for (int ks = 0; ks < 2; ks++)
            for (int r = 0; r < 2; r++) {
                int k0 = ks * 16 + 2 * t + r * 8;
                float v0 = 0.f, v1 = 0.f;
                if (g < 2) {
                    v0 = W2[k0 * 2 + g];
                    v1 = W2[(k0 + 1) * 2 + g];
                } else if (g < 4) {
                    int c = g - 2;
                    float w0f = W2[k0 * 2 + c];
                    float w1f = W2[(k0 + 1) * 2 + c];
                    v0 = (w0f - __half2float(__float2half_rn(w0f))) * 4096.f;
                    v1 = (w1f - __half2float(__float2half_rn(w1f))) * 4096.f;
                }
                __half2 h2 = __floats2half2_rn(v0, v1);
                g_B2frag[ks][r][tid] = *reinterpret_cast<unsigned int*>(&h2);
            }
    }
}

__device__ __forceinline__ void mma16816(float c[4],
                                         unsigned a0, unsigned a1, unsigned a2, unsigned a3,
                                         unsigned b0, unsigned b1)
{
    asm volatile(
        "mma.sync.aligned.m16n8k16.row.col.f32.f16.f16.f32 "
        "{%0,%1,%2,%3}, {%4,%5,%6,%7}, {%8,%9}, {%0,%1,%2,%3};"
        : "+f"(c[0]), "+f"(c[1]), "+f"(c[2]), "+f"(c[3])
        : "r"(a0), "r"(a1), "r"(a2), "r"(a3), "r"(b0), "r"(b1));
}

__device__ __forceinline__ void ldmatrix_x4(unsigned& a0, unsigned& a1,
                                            unsigned& a2, unsigned& a3,
                                            unsigned saddr)
{
    asm volatile(
        "ldmatrix.sync.aligned.m8n8.x4.shared.b16 {%0,%1,%2,%3}, [%4];"
        : "=r"(a0), "=r"(a1), "=r"(a2), "=r"(a3) : "r"(saddr));
}

// One warp = 64 samples. x loaded via coalesced float4 + smem transpose.
// Both 32-sample halves staged up front (one syncwarp) -> 4 independent tile
// chains. Hidden layer: f16 MMA (A=f16(F), B=f16(K)). Output layer: MMA on
// f16(relu(H)) with exact W2 via scaled-lo n-columns.
#define ROWH 24   // 48 B row stride: uint4-aligned, bank-conflict-free
__global__ void __launch_bounds__(256, 4)
qmlp_mma(const float* __restrict__ x,
         const float* __restrict__ b2,
         float* __restrict__ out, int B)
{
    __shared__ __align__(16) __half sA[8][2][32 * ROWH];
    __shared__ __align__(16) float  sX[8][192];

    int lane = threadIdx.x & 31;
    int warp = threadIdx.x >> 5;
    long long G = (long long)blockIdx.x * 8 + warp;
    long long wbase = G * 64;
    if (wbase >= B) return;

    int g = lane >> 2, t = lane & 3;
    float bias0 = __ldg(&b2[0]);
    float bias1 = __ldg(&b2[1]);

    // hoisted uniform fragments
    unsigned bf[4][2];
    #pragma unroll
    for (int nt = 0; nt < 4; nt++) {
        bf[nt][0] = __ldg(&g_Bfrag[nt][0][lane]);
        bf[nt][1] = __ldg(&g_Bfrag[nt][1][lane]);
    }
    unsigned b2f[2][2];
    #pragma unroll
    for (int ks = 0; ks < 2; ks++) {
        b2f[ks][0] = __ldg(&g_B2frag[ks][0][lane]);
        b2f[ks][1] = __ldg(&g_B2frag[ks][1][lane]);
    }

    int lm_row   = lane & 15;
    int lm_khalf = (lane >> 4) * 8;

    const __half2 hz = __floats2half2_rn(0.f, 0.f);
    const float SCL = 1.f / 4096.f;

    if (wbase + 64 <= B) {
        // ---- coalesced x load: 64 samples * 3 floats = 48 float4 ----
        const float4* xg = reinterpret_cast<const float4*>(x + wbase * 3);
        float4* sx = reinterpret_cast<float4*>(sX[warp]);
        sx[lane] = xg[lane];
        if (lane < 16) sx[32 + lane] = xg[32 + lane];
        __syncwarp();

        // ---- stage BOTH 32-sample halves, then one syncwarp ----
        #pragma unroll
        for (int it = 0; it < 2; it++) {
            int si = (it * 32 + lane) * 3;
            float xa = sX[warp][si];
            float xb = sX[warp][si + 1];      // x[...+2] is a global phase
            float s0n, c0n, s1n, c1n;
            __sincosf(xa, &s0n, &c0n);
            __sincosf(xb, &s1n, &c1n);
            float F[9] = { 1.f, c1n, s1n, c0n, c0n*c1n, c0n*s1n, s0n, s0n*c1n, s0n*s1n };

            unsigned w[8];
            __half2 h2;
            #define PACK(a, b) (h2 = __floats2half2_rn((a), (b)), *reinterpret_cast<unsigned*>(&h2))
            w[0] = PACK(F[0], F[1]);
            w[1] = PACK(F[2], F[3]);
            w[2] = PACK(F[4], F[5]);
            w[3] = PACK(F[6], F[7]);
            w[4] = PACK(F[8], 0.f);
            w[5] = 0u; w[6] = 0u; w[7] = 0u;
            #undef PACK

            uint4* rp = reinterpret_cast<uint4*>(&sA[warp][it][lane * ROWH]);
            rp[0] = make_uint4(w[0], w[1], w[2], w[3]);
            rp[1] = make_uint4(w[4], w[5], w[6], w[7]);
        }
        __syncwarp();

        // ---- 4 independent tile chains ----
        #pragma unroll
        for (int it = 0; it < 2; it++) {
            unsigned sbase = (unsigned)__cvta_generic_to_shared(&sA[warp][it][0]);
            #pragma unroll
            for (int tile = 0; tile < 2; tile++) {
                float acc[4][4];
                #pragma unroll
                for (int nt = 0; nt < 4; nt++)
                    #pragma unroll
                    for (int c = 0; c < 4; c++) acc[nt][c] = 0.f;

                unsigned lmaddr = sbase +
                    ((unsigned)(tile * 16 + lm_row) * (unsigned)ROWH + (unsigned)lm_khalf) * 2u;
                unsigned a0, a1, a2, a3;
                ldmatrix_x4(a0, a1, a2, a3, lmaddr);
                #pragma unroll
                for (int nt = 0; nt < 4; nt++)
                    mma16816(acc[nt], a0, a1, a2, a3, bf[nt][0], bf[nt][1]);

                unsigned hp[4][2];
                #pragma unroll
                for (int nt = 0; nt < 4; nt++) {
                    __half2 t01 = __floats2half2_rn(acc[nt][0], acc[nt][1]);
                    __half2 t23 = __floats2half2_rn(acc[nt][2], acc[nt][3]);
                    t01 = __hmax2(t01, hz);
                    t23 = __hmax2(t23, hz);
                    hp[nt][0] = *reinterpret_cast<unsigned*>(&t01);
                    hp[nt][1] = *reinterpret_cast<unsigned*>(&t23);
                }
                float o[4] = { 0.f, 0.f, 0.f, 0.f };
                mma16816(o, hp[0][0], hp[0][1], hp[1][0], hp[1][1], b2f[0][0], b2f[0][1]);
                mma16816(o, hp[2][0], hp[2][1], hp[3][0], hp[3][1], b2f[1][0], b2f[1][1]);

                // t=0: W2_hi (n=0,1); t=1: scaled W2_lo (n=2,3)
                float cr0 = __shfl_xor_sync(0xffffffffu, o[0], 1);
                float cr1 = __shfl_xor_sync(0xffffffffu, o[1], 1);
                float cr2 = __shfl_xor_sync(0xffffffffu, o[2], 1);
                float cr3 = __shfl_xor_sync(0xffffffffu, o[3], 1);

                if (t == 0) {
                    long long rr = wbase + (long long)it * 32 + tile * 16 + g;
                    float2* ov = reinterpret_cast<float2*>(out);
                    ov[rr]     = make_float2(fmaf(cr0, SCL, o[0]) + bias0,
                                             fmaf(cr1, SCL, o[1]) + bias1);
                    ov[rr + 8] = make_float2(fmaf(cr2, SCL, o[2]) + bias0,
                                             fmaf(cr3, SCL, o[3]) + bias1);
                }
            }
        }
    } else {
        // scalar fp32 tail
        for (long long s = wbase + lane; s < B; s += 32) {
            float xx0 = x[s * 3], xx1 = x[s * 3 + 1];
            float cc0, ss0, cc1, ss1;
            __sincosf(xx0, &ss0, &cc0);
            __sincosf(xx1, &ss1, &cc1);
            float o0 = bias0, o1 = bias1;
            for (int j = 0; j < NHID; j++) {
                const float* K = &g_const[j * 12];
                float t0 = K[0] + K[1]*cc1 + K[2]*ss1;
                float t1 = K[3] + K[4]*cc1 + K[5]*ss1;
                float t2 = K[6] + K[7]*cc1 + K[8]*ss1;
                float h = fmaxf(t0 + cc0*t1 + ss0*t2, 0.f);
                o0 += h * K[9];
                o1 += h * K[10];
            }
            out[s * 2]     = o0;
            out[s * 2 + 1] = o1;
        }
    }
}

extern "C" void kernel_launch(void* const* d_in, const int* in_sizes, int n_in,
                              void* d_out, int out_size)
{
    const float* x     = (const float*)d_in[0];
    const float* theta = (const float*)d_in[1];
    const float* W1    = (const float*)d_in[2];
    const float* b1    = (const float*)d_in[3];
    const float* W2    = (const float*)d_in[4];
    const float* b2    = (const float*)d_in[5];
    int B = in_sizes[0] / 3;

    setup_kernel<<<1, 32>>>(theta, W1, b1, W2);

    long long wgroups = ((long long)B + 63) / 64;
    int nblocks = (int)((wgroups + 7) / 8);
    qmlp_mma<<<nblocks, 256>>>(x, b2, (float*)d_out, B);
}